// round 8
// baseline (speedup 1.0000x reference)
#include <cuda_runtime.h>

// Problem constants
#define BSZ   16
#define MOUT  128
#define CBLK  8
#define NCH   1024
#define TLEN  2048
#define T4    (TLEN / 4)   // 512 float4 per row

// Fused kernel, barrier-free, 16-deep MLP:
//  Ax[b,m,t] = sum_c x[b, m*8+c, t] * tanh(blocks[m,c])
//  One CTA of 256 threads per (b,m) row; each thread produces TWO adjacent
//  float4s (t and t+256). All 16 streaming loads issue before any FMA; tanh
//  weights are computed per-warp (lanes 0-7) and shuffle-broadcast under the
//  load shadow. No __syncthreads, no shared memory.
//  CTAs with b==0 additionally write A_full row m (256 float4, one/thread).
__global__ void __launch_bounds__(256)
fused_kernel(const float* __restrict__ x,
             const float* __restrict__ blocks,
             float* __restrict__ ax_out,
             float* __restrict__ afull_out)
{
    const int bm   = blockIdx.x;          // 0 .. BSZ*MOUT-1
    const int m    = bm & (MOUT - 1);
    const int b    = bm >> 7;             // bm / MOUT
    const int lane = threadIdx.x & 31;
    const int tA   = threadIdx.x;         // first t-position
    const int tB   = threadIdx.x + 256;   // second t-position

    const float4* __restrict__ xb =
        reinterpret_cast<const float4*>(x + ((size_t)b * NCH + (size_t)m * CBLK) * TLEN);
    float4* __restrict__ ob =
        reinterpret_cast<float4*>(ax_out + ((size_t)b * MOUT + m) * TLEN);

    // ---- Issue ALL 16 streaming loads first (evict-first; touched once) ----
    float4 a0 = __ldcs(xb + 0 * T4 + tA);
    float4 a1 = __ldcs(xb + 1 * T4 + tA);
    float4 a2 = __ldcs(xb + 2 * T4 + tA);
    float4 a3 = __ldcs(xb + 3 * T4 + tA);
    float4 a4 = __ldcs(xb + 4 * T4 + tA);
    float4 a5 = __ldcs(xb + 5 * T4 + tA);
    float4 a6 = __ldcs(xb + 6 * T4 + tA);
    float4 a7 = __ldcs(xb + 7 * T4 + tA);
    float4 c0 = __ldcs(xb + 0 * T4 + tB);
    float4 c1 = __ldcs(xb + 1 * T4 + tB);
    float4 c2 = __ldcs(xb + 2 * T4 + tB);
    float4 c3 = __ldcs(xb + 3 * T4 + tB);
    float4 c4 = __ldcs(xb + 4 * T4 + tB);
    float4 c5 = __ldcs(xb + 5 * T4 + tB);
    float4 c6 = __ldcs(xb + 6 * T4 + tB);
    float4 c7 = __ldcs(xb + 7 * T4 + tB);

    // ---- Compute weights under the load shadow: lane-parallel tanh + shfl ----
    const float wv = tanhf(__ldg(blocks + m * CBLK + (lane & 7)));
    const float w0 = __shfl_sync(0xffffffffu, wv, 0);
    const float w1 = __shfl_sync(0xffffffffu, wv, 1);
    const float w2 = __shfl_sync(0xffffffffu, wv, 2);
    const float w3 = __shfl_sync(0xffffffffu, wv, 3);
    const float w4 = __shfl_sync(0xffffffffu, wv, 4);
    const float w5 = __shfl_sync(0xffffffffu, wv, 5);
    const float w6 = __shfl_sync(0xffffffffu, wv, 6);
    const float w7 = __shfl_sync(0xffffffffu, wv, 7);

    float4 accA;
    accA.x = a0.x * w0;  accA.y = a0.y * w0;  accA.z = a0.z * w0;  accA.w = a0.w * w0;
    accA.x += a1.x * w1; accA.y += a1.y * w1; accA.z += a1.z * w1; accA.w += a1.w * w1;
    accA.x += a2.x * w2; accA.y += a2.y * w2; accA.z += a2.z * w2; accA.w += a2.w * w2;
    accA.x += a3.x * w3; accA.y += a3.y * w3; accA.z += a3.z * w3; accA.w += a3.w * w3;
    accA.x += a4.x * w4; accA.y += a4.y * w4; accA.z += a4.z * w4; accA.w += a4.w * w4;
    accA.x += a5.x * w5; accA.y += a5.y * w5; accA.z += a5.z * w5; accA.w += a5.w * w5;
    accA.x += a6.x * w6; accA.y += a6.y * w6; accA.z += a6.z * w6; accA.w += a6.w * w6;
    accA.x += a7.x * w7; accA.y += a7.y * w7; accA.z += a7.z * w7; accA.w += a7.w * w7;
    __stcs(ob + tA, accA);

    float4 accB;
    accB.x = c0.x * w0;  accB.y = c0.y * w0;  accB.z = c0.z * w0;  accB.w = c0.w * w0;
    accB.x += c1.x * w1; accB.y += c1.y * w1; accB.z += c1.z * w1; accB.w += c1.w * w1;
    accB.x += c2.x * w2; accB.y += c2.y * w2; accB.z += c2.z * w2; accB.w += c2.w * w2;
    accB.x += c3.x * w3; accB.y += c3.y * w3; accB.z += c3.z * w3; accB.w += c3.w * w3;
    accB.x += c4.x * w4; accB.y += c4.y * w4; accB.z += c4.z * w4; accB.w += c4.w * w4;
    accB.x += c5.x * w5; accB.y += c5.y * w5; accB.z += c5.z * w5; accB.w += c5.w * w5;
    accB.x += c6.x * w6; accB.y += c6.y * w6; accB.z += c6.z * w6; accB.w += c6.w * w6;
    accB.x += c7.x * w7; accB.y += c7.y * w7; accB.z += c7.z * w7; accB.w += c7.w * w7;
    __stcs(ob + tB, accB);

    // A_full[m, j] = (j>>3 == m) ? tanh(blocks[j]) : 0 — b==0 CTAs, 256 float4/row.
    if (b == 0) {
        const int j0 = threadIdx.x * 4;
        float4 a = make_float4(0.f, 0.f, 0.f, 0.f);
        if ((j0 >> 3) == m) {
            if (j0 & 4) { a.x = w4; a.y = w5; a.z = w6; a.w = w7; }
            else        { a.x = w0; a.y = w1; a.z = w2; a.w = w3; }
        }
        reinterpret_cast<float4*>(afull_out + (size_t)m * NCH)[threadIdx.x] = a;
    }
}

extern "C" void kernel_launch(void* const* d_in, const int* in_sizes, int n_in,
                              void* d_out, int out_size)
{
    const float* x      = (const float*)d_in[0];
    const float* blocks = (const float*)d_in[1];
    float* out = (float*)d_out;

    // Output layout: Ax (B*M*T floats) followed by A_full (M*NCH floats)
    float* ax_out    = out;
    float* afull_out = out + (size_t)BSZ * MOUT * TLEN;

    fused_kernel<<<BSZ * MOUT, 256>>>(x, blocks, ax_out, afull_out);
}

// round 9
// speedup vs baseline: 1.0830x; 1.0830x over previous
#include <cuda_runtime.h>

// Problem constants
#define BSZ   16
#define MOUT  128
#define CBLK  8
#define NCH   1024
#define TLEN  2048
#define T4    (TLEN / 4)   // 512 float4 per row

// Fused kernel, flattened & barrier-free (R6 structure), write-back stores:
//  Ax[b,m,t] = sum_c x[b, m*8+c, t] * tanh(blocks[m,c])
//  One CTA of 512 threads per (b,m) row; each thread produces one float4.
//  The 8 streaming loads issue FIRST; tanh weights are computed per-warp
//  (lanes 0-7) and shuffle-broadcast while the loads are in flight — no
//  __syncthreads, no shared memory.
//  Loads: __ldcs (evict-first — x touched exactly once).
//  Stores: default write-back — output absorbs into L2, DRAM writeback is
//  scheduled lazily instead of interleaving with the read stream.
//  CTAs with b==0 additionally write A_full row m (first 256 threads).
__global__ void __launch_bounds__(512, 4)
fused_kernel(const float* __restrict__ x,
             const float* __restrict__ blocks,
             float* __restrict__ ax_out,
             float* __restrict__ afull_out)
{
    const int bm   = blockIdx.x;          // 0 .. BSZ*MOUT-1
    const int m    = bm & (MOUT - 1);
    const int b    = bm >> 7;             // bm / MOUT
    const int lane = threadIdx.x & 31;
    const int t    = threadIdx.x;         // 0 .. 511 — one float4 per thread

    const float4* __restrict__ xb =
        reinterpret_cast<const float4*>(x + ((size_t)b * NCH + (size_t)m * CBLK) * TLEN);
    float4* __restrict__ ob =
        reinterpret_cast<float4*>(ax_out + ((size_t)b * MOUT + m) * TLEN);

    // ---- Issue all 8 streaming loads first (evict-first; touched once) ----
    float4 v0 = __ldcs(xb + 0 * T4 + t);
    float4 v1 = __ldcs(xb + 1 * T4 + t);
    float4 v2 = __ldcs(xb + 2 * T4 + t);
    float4 v3 = __ldcs(xb + 3 * T4 + t);
    float4 v4 = __ldcs(xb + 4 * T4 + t);
    float4 v5 = __ldcs(xb + 5 * T4 + t);
    float4 v6 = __ldcs(xb + 6 * T4 + t);
    float4 v7 = __ldcs(xb + 7 * T4 + t);

    // ---- Compute weights under the load shadow: lane-parallel tanh + shfl ----
    const float wv = tanhf(__ldg(blocks + m * CBLK + (lane & 7)));
    const float w0 = __shfl_sync(0xffffffffu, wv, 0);
    const float w1 = __shfl_sync(0xffffffffu, wv, 1);
    const float w2 = __shfl_sync(0xffffffffu, wv, 2);
    const float w3 = __shfl_sync(0xffffffffu, wv, 3);
    const float w4 = __shfl_sync(0xffffffffu, wv, 4);
    const float w5 = __shfl_sync(0xffffffffu, wv, 5);
    const float w6 = __shfl_sync(0xffffffffu, wv, 6);
    const float w7 = __shfl_sync(0xffffffffu, wv, 7);

    float4 acc;
    acc.x = v0.x * w0;  acc.y = v0.y * w0;  acc.z = v0.z * w0;  acc.w = v0.w * w0;
    acc.x += v1.x * w1; acc.y += v1.y * w1; acc.z += v1.z * w1; acc.w += v1.w * w1;
    acc.x += v2.x * w2; acc.y += v2.y * w2; acc.z += v2.z * w2; acc.w += v2.w * w2;
    acc.x += v3.x * w3; acc.y += v3.y * w3; acc.z += v3.z * w3; acc.w += v3.w * w3;
    acc.x += v4.x * w4; acc.y += v4.y * w4; acc.z += v4.z * w4; acc.w += v4.w * w4;
    acc.x += v5.x * w5; acc.y += v5.y * w5; acc.z += v5.z * w5; acc.w += v5.w * w5;
    acc.x += v6.x * w6; acc.y += v6.y * w6; acc.z += v6.z * w6; acc.w += v6.w * w6;
    acc.x += v7.x * w7; acc.y += v7.y * w7; acc.z += v7.z * w7; acc.w += v7.w * w7;
    ob[t] = acc;   // default write-back store — L2-absorbed

    // A_full[m, j] = (j>>3 == m) ? tanh(blocks[j]) : 0 — b==0 CTAs, 256 float4/row.
    if (b == 0 && threadIdx.x < 256) {
        const int j0 = threadIdx.x * 4;
        float4 a = make_float4(0.f, 0.f, 0.f, 0.f);
        if ((j0 >> 3) == m) {
            if (j0 & 4) { a.x = w4; a.y = w5; a.z = w6; a.w = w7; }
            else        { a.x = w0; a.y = w1; a.z = w2; a.w = w3; }
        }
        reinterpret_cast<float4*>(afull_out + (size_t)m * NCH)[threadIdx.x] = a;
    }
}

extern "C" void kernel_launch(void* const* d_in, const int* in_sizes, int n_in,
                              void* d_out, int out_size)
{
    const float* x      = (const float*)d_in[0];
    const float* blocks = (const float*)d_in[1];
    float* out = (float*)d_out;

    // Output layout: Ax (B*M*T floats) followed by A_full (M*NCH floats)
    float* ax_out    = out;
    float* afull_out = out + (size_t)BSZ * MOUT * TLEN;

    fused_kernel<<<BSZ * MOUT, 512>>>(x, blocks, ax_out, afull_out);
}